// round 7
// baseline (speedup 1.0000x reference)
#include <cuda_runtime.h>
#include <cuda_bf16.h>
#include <mma.h>
#include <math.h>

using namespace nvcuda;

#define B 128
#define T 200
#define V 50257
#define H 256
#define EDIM 128
#define TWOH 512
#define GIN 640           // 2H + E
#define G3 768            // 3H
#define MAXOOV 50
#define OV (V + MAXOOV)   // 50307

static const size_t OFF_H = (size_t)B * OV;
static const size_t OFF_S = (size_t)B * OV + (size_t)B * H;

// ---------------- device scratch ----------------
__device__ float g_score_g[(size_t)B * V];
__device__ float g_score_c[B * T];
__device__ float g_gin[B * GIN];
__device__ float g_gi[B * G3];
__device__ float g_gh[B * G3];
__device__ float g_prev[B * H];
__device__ float g_hid[B * H];
__device__ float g_rmax[B];
__device__ float g_rsum[B];

// ---------------- fp32 -> bf16 hi/lo split ----------------
__device__ __forceinline__ void bsplit(float x, float y, unsigned& h, unsigned& l) {
    __nv_bfloat16 hx = __float2bfloat16(x);
    __nv_bfloat16 hy = __float2bfloat16(y);
    __nv_bfloat16 lx = __float2bfloat16(x - __bfloat162float(hx));
    __nv_bfloat16 ly = __float2bfloat16(y - __bfloat162float(hy));
    h = ((unsigned)__bfloat16_as_ushort(hy) << 16) | (unsigned)__bfloat16_as_ushort(hx);
    l = ((unsigned)__bfloat16_as_ushort(ly) << 16) | (unsigned)__bfloat16_as_ushort(lx);
}

#define SP 40  // smem row stride in bf16 elements (32 cols + 8 pad), 16B-aligned rows

// load tile (rows x 32 f32) from src (row stride strideE elems), split hi/lo into smem.
// rows >= validRows are zeroed.
__device__ __forceinline__ void load_split(const float* __restrict__ src, int strideE,
                                           int rows, int validRows,
                                           __nv_bfloat16* __restrict__ hi,
                                           __nv_bfloat16* __restrict__ lo,
                                           int tid, int nt) {
    for (int i = tid; i < rows * 8; i += nt) {
        int r = i >> 3, c4 = (i & 7) << 2;
        float4 v = make_float4(0.f, 0.f, 0.f, 0.f);
        if (r < validRows) v = *(const float4*)(src + (long long)r * strideE + c4);
        unsigned h0, l0, h1, l1;
        bsplit(v.x, v.y, h0, l0);
        bsplit(v.z, v.w, h1, l1);
        *(uint2*)(hi + r * SP + c4) = make_uint2(h0, h1);
        *(uint2*)(lo + r * SP + c4) = make_uint2(l0, l1);
    }
}

// ============ WMMA GEMM: C[128,N] = A[128,K] @ Bt[N,K]^T + bias ============
// 256 threads (8 warps, 2m x 4n), block tile 128x128, BK=32, K multiple of 32.
// dyn smem: union of stage (40KB) and epilogue Cs 128x136 f32 (69632B).
#define G1_SMEM 69632

__global__ void __launch_bounds__(256) tc_gemm1(const float* __restrict__ A,
                                                const float* __restrict__ Bt,
                                                const float* __restrict__ bias,
                                                float* __restrict__ C, int N, int K) {
    extern __shared__ char smc[];
    __nv_bfloat16* Ah = (__nv_bfloat16*)smc;
    __nv_bfloat16* Al = Ah + 128 * SP;
    __nv_bfloat16* Bh = Al + 128 * SP;
    __nv_bfloat16* Bl = Bh + 128 * SP;
    const int tid = threadIdx.x, wid = tid >> 5;
    const int wm = wid & 1, wn = wid >> 1;   // warp tile 64(m) x 32(n)
    const int n0 = blockIdx.x * 128;
    int vB = N - n0; if (vB > 128) vB = 128;

    wmma::fragment<wmma::accumulator, 16, 16, 16, float> acc[4][2];
    #pragma unroll
    for (int i = 0; i < 4; i++)
        #pragma unroll
        for (int j = 0; j < 2; j++) wmma::fill_fragment(acc[i][j], 0.0f);

    for (int kk = 0; kk < K; kk += 32) {
        __syncthreads();
        load_split(A + kk, K, 128, 128, Ah, Al, tid, 256);
        load_split(Bt + (long long)n0 * K + kk, K, 128, vB, Bh, Bl, tid, 256);
        __syncthreads();
        #pragma unroll
        for (int p = 0; p < 3; p++) {
            const __nv_bfloat16* Ap = (p == 2) ? Al : Ah;
            const __nv_bfloat16* Bp = (p == 1) ? Bl : Bh;
            #pragma unroll
            for (int ks = 0; ks < 2; ks++) {
                wmma::fragment<wmma::matrix_a, 16, 16, 16, __nv_bfloat16, wmma::row_major> fa[4];
                wmma::fragment<wmma::matrix_b, 16, 16, 16, __nv_bfloat16, wmma::col_major> fb[2];
                #pragma unroll
                for (int i = 0; i < 4; i++)
                    wmma::load_matrix_sync(fa[i], Ap + (wm * 64 + i * 16) * SP + ks * 16, SP);
                #pragma unroll
                for (int j = 0; j < 2; j++)
                    wmma::load_matrix_sync(fb[j], Bp + (wn * 32 + j * 16) * SP + ks * 16, SP);
                #pragma unroll
                for (int i = 0; i < 4; i++)
                    #pragma unroll
                    for (int j = 0; j < 2; j++)
                        wmma::mma_sync(acc[i][j], fa[i], fb[j], acc[i][j]);
            }
        }
    }
    __syncthreads();
    float* Cs = (float*)smc;  // 128 x 136
    #pragma unroll
    for (int i = 0; i < 4; i++)
        #pragma unroll
        for (int j = 0; j < 2; j++)
            wmma::store_matrix_sync(Cs + (wm * 64 + i * 16) * 136 + wn * 32 + j * 16,
                                    acc[i][j], 136, wmma::mem_row_major);
    __syncthreads();
    for (int i = tid; i < 128 * 128; i += 256) {
        int r = i >> 7, c = i & 127;
        if (n0 + c < N) C[(long long)r * N + n0 + c] = Cs[r * 136 + c] + bias[n0 + c];
    }
}

// ===== fused GEMM2: ep = tanh(enc[128,512] @ Wc[256,512]^T + b); sc = tanh(ep . hd) + mask =====
// 512 threads (16 warps, 4m x 4n), block tile 128x256, BK=32.
// smem: union(stage 60KB, Cs 128x264 f32 = 135168) + sh_hd 2048 = 137216.
#define F_CS 135168
#define F_SMEM 137216

__global__ void __launch_bounds__(512) tc_gemm2_fused(const float* __restrict__ enc,
                                                      const float* __restrict__ Wc,
                                                      const float* __restrict__ Wc_b,
                                                      const float* __restrict__ hd,
                                                      const int* __restrict__ idxs,
                                                      float* __restrict__ sc) {
    extern __shared__ char smc[];
    __nv_bfloat16* Ah = (__nv_bfloat16*)smc;
    __nv_bfloat16* Al = Ah + 128 * SP;
    __nv_bfloat16* Bh = Al + 128 * SP;
    __nv_bfloat16* Bl = Bh + 256 * SP;
    float* sh_hd = (float*)(smc + F_CS);
    const int tid = threadIdx.x, wid = tid >> 5;
    const int wm = wid & 3, wn = wid >> 2;   // warp tile 32(m) x 64(n)
    const int g0 = blockIdx.x * 128;
    const int bA = g0 / T, bB = (g0 + 127) / T;

    for (int i = tid; i < 512; i += 512)
        sh_hd[i] = hd[(size_t)((i < 256) ? bA : bB) * H + (i & 255)];

    wmma::fragment<wmma::accumulator, 16, 16, 16, float> acc[2][4];
    #pragma unroll
    for (int i = 0; i < 2; i++)
        #pragma unroll
        for (int j = 0; j < 4; j++) wmma::fill_fragment(acc[i][j], 0.0f);

    for (int kk = 0; kk < TWOH; kk += 32) {
        __syncthreads();
        load_split(enc + (long long)g0 * TWOH + kk, TWOH, 128, 128, Ah, Al, tid, 512);
        load_split(Wc + kk, TWOH, 256, 256, Bh, Bl, tid, 512);
        __syncthreads();
        #pragma unroll
        for (int p = 0; p < 3; p++) {
            const __nv_bfloat16* Ap = (p == 2) ? Al : Ah;
            const __nv_bfloat16* Bp = (p == 1) ? Bl : Bh;
            #pragma unroll
            for (int ks = 0; ks < 2; ks++) {
                wmma::fragment<wmma::matrix_a, 16, 16, 16, __nv_bfloat16, wmma::row_major> fa[2];
                wmma::fragment<wmma::matrix_b, 16, 16, 16, __nv_bfloat16, wmma::col_major> fb[4];
                #pragma unroll
                for (int i = 0; i < 2; i++)
                    wmma::load_matrix_sync(fa[i], Ap + (wm * 32 + i * 16) * SP + ks * 16, SP);
                #pragma unroll
                for (int j = 0; j < 4; j++)
                    wmma::load_matrix_sync(fb[j], Bp + (wn * 64 + j * 16) * SP + ks * 16, SP);
                #pragma unroll
                for (int i = 0; i < 2; i++)
                    #pragma unroll
                    for (int j = 0; j < 4; j++)
                        wmma::mma_sync(acc[i][j], fa[i], fb[j], acc[i][j]);
            }
        }
    }
    __syncthreads();
    float* Cs = (float*)smc;  // 128 x 264
    #pragma unroll
    for (int i = 0; i < 2; i++)
        #pragma unroll
        for (int j = 0; j < 4; j++)
            wmma::store_matrix_sync(Cs + (wm * 32 + i * 16) * 264 + wn * 64 + j * 16,
                                    acc[i][j], 264, wmma::mem_row_major);
    __syncthreads();

    // fused epilogue: tanh(+bias), dot with hd, quad-reduce, tanh, mask
    int row = tid >> 2, q = tid & 3;
    int g = g0 + row;
    int hsel = ((g / T) == bA) ? 0 : 256;
    float partial = 0.f;
    #pragma unroll 8
    for (int c = q * 64; c < q * 64 + 64; c++) {
        float v = tanhf(Cs[row * 264 + c] + Wc_b[c]);
        partial += v * sh_hd[hsel + c];
    }
    partial += __shfl_xor_sync(0xffffffffu, partial, 1);
    partial += __shfl_xor_sync(0xffffffffu, partial, 2);
    if (q == 0) {
        float v = tanhf(partial);
        if (idxs[g] == 0) v -= 10000.0f;
        sc[g] = v;
    }
}

// ---------------- prep ----------------
__global__ void prep_kernel(const int* __restrict__ dec, const float* __restrict__ enc,
                            const float* __restrict__ prev, const float* __restrict__ selr,
                            const int* __restrict__ stepp, const float* __restrict__ emb,
                            const float* __restrict__ Wi_w, const float* __restrict__ Wi_b,
                            float* __restrict__ pv, float* __restrict__ gin) {
    int b = blockIdx.x;
    int tid = threadIdx.x; // 512
    int step = stepp ? *stepp : 1;
    __shared__ float se[TWOH];
    if (step != 0) {
        gin[(size_t)b * GIN + tid] = selr[(size_t)b * TWOH + tid];
        if (tid < H) pv[b * H + tid] = prev[b * H + tid];
    } else {
        gin[(size_t)b * GIN + tid] = 0.0f;
        se[tid] = enc[((size_t)b * T + (T - 1)) * TWOH + tid];
        __syncthreads();
        if (tid < H) {
            float s = Wi_b[tid];
            #pragma unroll 8
            for (int k = 0; k < TWOH; k++) s += se[k] * Wi_w[tid * TWOH + k];
            pv[b * H + tid] = s;
        }
    }
    if (tid < EDIM) gin[(size_t)b * GIN + TWOH + tid] = emb[(size_t)dec[b] * EDIM + tid];
}

// ---------------- GRU gates ----------------
__global__ void gate_kernel(const float* __restrict__ gi, const float* __restrict__ gh,
                            const float* __restrict__ pv, float* __restrict__ hdo,
                            float* __restrict__ out) {
    int b = blockIdx.x, j = threadIdx.x;
    const float* gib = gi + (size_t)b * G3;
    const float* ghb = gh + (size_t)b * G3;
    float r = 1.0f / (1.0f + expf(-(gib[j] + ghb[j])));
    float z = 1.0f / (1.0f + expf(-(gib[H + j] + ghb[H + j])));
    float n = tanhf(gib[2 * H + j] + r * ghb[2 * H + j]);
    float h = (1.0f - z) * n + z * pv[b * H + j];
    hdo[b * H + j] = h;
    out[OFF_H + (size_t)b * H + j] = h;
}

// ---------------- joint softmax row reduce ----------------
__global__ void rowreduce_kernel(const float* __restrict__ sg, const float* __restrict__ sc,
                                 float* __restrict__ rmax, float* __restrict__ rsum) {
    int b = blockIdx.x, tid = threadIdx.x;
    const int total = V + T;
    float m = -INFINITY, s = 0.0f;
    for (int j = tid; j < total; j += 256) {
        float v = (j < V) ? sg[(size_t)b * V + j] : sc[b * T + (j - V)];
        if (v > m) { s = s * expf(m - v) + 1.0f; m = v; }
        else       { s += expf(v - m); }
    }
    __shared__ float smx[256], ssm[256];
    smx[tid] = m; ssm[tid] = s;
    __syncthreads();
    for (int st = 128; st > 0; st >>= 1) {
        if (tid < st) {
            float m2 = smx[tid + st], s2 = ssm[tid + st];
            float M = fmaxf(smx[tid], m2);
            ssm[tid] = ssm[tid] * expf(smx[tid] - M) + s2 * expf(m2 - M);
            smx[tid] = M;
        }
        __syncthreads();
    }
    if (tid == 0) { rmax[b] = smx[0]; rsum[b] = ssm[0]; }
}

// ---------------- prob_out base ----------------
__global__ void prob_kernel(const float* __restrict__ sg, const float* __restrict__ rmax,
                            const float* __restrict__ rsum, float* __restrict__ out) {
    int b = blockIdx.y;
    int j = blockIdx.x * 256 + threadIdx.x;
    if (j >= OV) return;
    float m = rmax[b], inv = 1.0f / rsum[b];
    out[(size_t)b * OV + j] = (j < V) ? expf(sg[(size_t)b * V + j] - m) * inv : 0.0001f;
}

// ---------------- scatter copy probs ----------------
__global__ void scatter_kernel(const float* __restrict__ sc, const int* __restrict__ idxs,
                               const float* __restrict__ rmax, const float* __restrict__ rsum,
                               float* __restrict__ out) {
    int i = blockIdx.x * 256 + threadIdx.x;
    if (i >= B * T) return;
    int b = i / T;
    float p = expf(sc[i] - rmax[b]) / rsum[b];
    atomicAdd(&out[(size_t)b * OV + idxs[i]], p);
}

// ---------------- selective read ----------------
__global__ void selread_kernel(const float* __restrict__ sc, const int* __restrict__ idxs,
                               const int* __restrict__ dec, const float* __restrict__ enc,
                               const float* __restrict__ rmax, const float* __restrict__ rsum,
                               float* __restrict__ out) {
    int b = blockIdx.x, tid = threadIdx.x;
    __shared__ int s_cnt;
    __shared__ int s_ts[T];
    __shared__ float s_w[T];
    if (tid == 0) {
        int d = dec[b];
        int cnt = 0;
        float m = rmax[b], inv = 1.0f / rsum[b];
        for (int t = 0; t < T; t++) {
            if (idxs[b * T + t] == d) {
                s_ts[cnt] = t;
                s_w[cnt] = expf(sc[b * T + t] - m) * inv;
                cnt++;
            }
        }
        s_cnt = cnt;
    }
    __syncthreads();
    int cnt = s_cnt;
    float scale = (cnt > 1) ? (1.0f / (float)cnt) : 1.0f;
    for (int e = tid; e < TWOH; e += 256) {
        float acc = 0.0f;
        for (int i = 0; i < cnt; i++)
            acc += s_w[i] * enc[((size_t)b * T + s_ts[i]) * TWOH + e];
        out[OFF_S + (size_t)b * TWOH + e] = acc * scale;
    }
}

// ---------------- launch ----------------
extern "C" void kernel_launch(void* const* d_in, const int* in_sizes, int n_in,
                              void* d_out, int out_size) {
    int o = (n_in >= 17) ? 0 : -1;
    const int*   dec   = (const int*)d_in[0];
    const float* enc   = (const float*)d_in[1];
    const int*   idxs  = (const int*)d_in[2];
    const float* prev  = (const float*)d_in[3];
    const float* selr  = (const float*)d_in[4];
    const int*   stepp = (o == 0) ? (const int*)d_in[5] : nullptr;
    const float* emb   = (const float*)d_in[6 + o];
    const float* W_ih  = (const float*)d_in[7 + o];
    const float* W_hh  = (const float*)d_in[8 + o];
    const float* b_ih  = (const float*)d_in[9 + o];
    const float* b_hh  = (const float*)d_in[10 + o];
    const float* Wi_w  = (const float*)d_in[11 + o];
    const float* Wi_b  = (const float*)d_in[12 + o];
    const float* Wg_w  = (const float*)d_in[13 + o];
    const float* Wg_b  = (const float*)d_in[14 + o];
    const float* Wc_w  = (const float*)d_in[15 + o];
    const float* Wc_b  = (const float*)d_in[16 + o];
    float* out = (float*)d_out;

    float *sg, *sc, *gin, *gi, *gh, *pv, *hd, *rmax, *rsum;
    cudaGetSymbolAddress((void**)&sg,   g_score_g);
    cudaGetSymbolAddress((void**)&sc,   g_score_c);
    cudaGetSymbolAddress((void**)&gin,  g_gin);
    cudaGetSymbolAddress((void**)&gi,   g_gi);
    cudaGetSymbolAddress((void**)&gh,   g_gh);
    cudaGetSymbolAddress((void**)&pv,   g_prev);
    cudaGetSymbolAddress((void**)&hd,   g_hid);
    cudaGetSymbolAddress((void**)&rmax, g_rmax);
    cudaGetSymbolAddress((void**)&rsum, g_rsum);

    cudaFuncSetAttribute(tc_gemm1, cudaFuncAttributeMaxDynamicSharedMemorySize, G1_SMEM);
    cudaFuncSetAttribute(tc_gemm2_fused, cudaFuncAttributeMaxDynamicSharedMemorySize, F_SMEM);

    // 1. step handling + embedding gather + gru_in assembly
    prep_kernel<<<B, 512>>>(dec, enc, prev, selr, stepp, emb, Wi_w, Wi_b, pv, gin);
    // 2. GRU projections (HMMA, split-bf16 ~fp32 accuracy)
    tc_gemm1<<<G3 / 128, 256, G1_SMEM>>>(gin, W_ih, b_ih, gi, G3, GIN);
    tc_gemm1<<<G3 / 128, 256, G1_SMEM>>>(pv, W_hh, b_hh, gh, G3, H);
    // 3. gates -> decode_hidden
    gate_kernel<<<B, H>>>(gi, gh, pv, hd, out);
    // 4. generation scores [128 x 50257]
    tc_gemm1<<<(V + 127) / 128, 256, G1_SMEM>>>(hd, Wg_w, Wg_b, sg, V, H);
    // 5+6. enc projection + tanh + copy-score dot + tanh + mask, fused
    tc_gemm2_fused<<<(B * T) / 128, 512, F_SMEM>>>(enc, Wc_w, Wc_b, hd, idxs, sc);
    // 7. joint softmax stats
    rowreduce_kernel<<<B, 256>>>(sg, sc, rmax, rsum);
    // 8. prob_out base
    prob_kernel<<<dim3((OV + 255) / 256, B), 256>>>(sg, rmax, rsum, out);
    // 9. scatter-add copy probs
    scatter_kernel<<<(B * T + 255) / 256, 256>>>(sc, idxs, rmax, rsum, out);
    // 10. selective read
    selread_kernel<<<B, 256>>>(sc, idxs, dec, enc, rmax, rsum, out);
}

// round 11
// speedup vs baseline: 1.6473x; 1.6473x over previous
#include <cuda_runtime.h>
#include <cuda_bf16.h>
#include <mma.h>
#include <math.h>

using namespace nvcuda;

#define B 128
#define T 200
#define V 50257
#define H 256
#define EDIM 128
#define TWOH 512
#define GIN 640           // 2H + E
#define G3 768            // 3H
#define MAXOOV 50
#define OV (V + MAXOOV)   // 50307

static const size_t OFF_H = (size_t)B * OV;
static const size_t OFF_S = (size_t)B * OV + (size_t)B * H;

// ---------------- device scratch ----------------
__device__ float g_score_g[(size_t)B * V];
__device__ float g_score_c[B * T];
__device__ float g_gin[B * GIN];
__device__ float g_gi[B * G3];
__device__ float g_gh[B * G3];
__device__ float g_prev[B * H];
__device__ float g_hid[B * H];
__device__ float g_rmax[B];
__device__ float g_rsum[B];

// ---------------- fast transcendentals ----------------
// __expf: MUFU.EX2-based, rel err ~1e-6 -- plenty for 1e-3 gate.
__device__ __forceinline__ float ftanh(float x) {
    float a = fabsf(x);
    float t = __expf(-2.0f * a);
    float r = __fdividef(1.0f - t, 1.0f + t);
    return copysignf(r, x);
}

// ---------------- fp32 -> bf16 hi/lo split ----------------
__device__ __forceinline__ void bsplit(float x, float y, unsigned& h, unsigned& l) {
    __nv_bfloat16 hx = __float2bfloat16(x);
    __nv_bfloat16 hy = __float2bfloat16(y);
    __nv_bfloat16 lx = __float2bfloat16(x - __bfloat162float(hx));
    __nv_bfloat16 ly = __float2bfloat16(y - __bfloat162float(hy));
    h = ((unsigned)__bfloat16_as_ushort(hy) << 16) | (unsigned)__bfloat16_as_ushort(hx);
    l = ((unsigned)__bfloat16_as_ushort(ly) << 16) | (unsigned)__bfloat16_as_ushort(lx);
}

#define SP 40  // smem row stride in bf16 elements (32 cols + 8 pad)

__device__ __forceinline__ void store_split(float4 v, __nv_bfloat16* __restrict__ hi,
                                            __nv_bfloat16* __restrict__ lo, int r, int c4) {
    unsigned h0, l0, h1, l1;
    bsplit(v.x, v.y, h0, l0);
    bsplit(v.z, v.w, h1, l1);
    *(uint2*)(hi + r * SP + c4) = make_uint2(h0, h1);
    *(uint2*)(lo + r * SP + c4) = make_uint2(l0, l1);
}

// ============ WMMA GEMM: C[128,N] = A[128,K] @ Bt[N,K]^T + bias ============
// 256 threads (8 warps, 2m x 4n), block tile 128x128, BK=32, K multiple of 32.
// Register-prefetch pipelining: LDG for tile k+1 issued before MMA phase of tile k.
#define G1_SMEM 69632

__global__ void __launch_bounds__(256) tc_gemm1(const float* __restrict__ A,
                                                const float* __restrict__ Bt,
                                                const float* __restrict__ bias,
                                                float* __restrict__ C, int N, int K) {
    extern __shared__ char smc[];
    __nv_bfloat16* Ah = (__nv_bfloat16*)smc;
    __nv_bfloat16* Al = Ah + 128 * SP;
    __nv_bfloat16* Bh = Al + 128 * SP;
    __nv_bfloat16* Bl = Bh + 128 * SP;
    const int tid = threadIdx.x, wid = tid >> 5;
    const int wm = wid & 1, wn = wid >> 1;   // warp tile 64(m) x 32(n)
    const int n0 = blockIdx.x * 128;
    int vB = N - n0; if (vB > 128) vB = 128;

    // per-thread quad coords (4 A quads, 4 B quads)
    int qr[4], qc[4];
    #pragma unroll
    for (int j = 0; j < 4; j++) { int i = tid + j * 256; qr[j] = i >> 3; qc[j] = (i & 7) << 2; }

    float4 pa[4], pb[4];
    #pragma unroll
    for (int j = 0; j < 4; j++) {
        pa[j] = *(const float4*)(A + (long long)qr[j] * K + qc[j]);
        pb[j] = (qr[j] < vB) ? *(const float4*)(Bt + (long long)(n0 + qr[j]) * K + qc[j])
                             : make_float4(0.f, 0.f, 0.f, 0.f);
    }

    wmma::fragment<wmma::accumulator, 16, 16, 16, float> acc[4][2];
    #pragma unroll
    for (int i = 0; i < 4; i++)
        #pragma unroll
        for (int j = 0; j < 2; j++) wmma::fill_fragment(acc[i][j], 0.0f);

    for (int kk = 0; kk < K; kk += 32) {
        __syncthreads();  // previous MMA phase done with smem
        #pragma unroll
        for (int j = 0; j < 4; j++) {
            store_split(pa[j], Ah, Al, qr[j], qc[j]);
            store_split(pb[j], Bh, Bl, qr[j], qc[j]);
        }
        int kn = kk + 32;
        if (kn < K) {
            #pragma unroll
            for (int j = 0; j < 4; j++) {
                pa[j] = *(const float4*)(A + (long long)qr[j] * K + kn + qc[j]);
                pb[j] = (qr[j] < vB) ? *(const float4*)(Bt + (long long)(n0 + qr[j]) * K + kn + qc[j])
                                     : make_float4(0.f, 0.f, 0.f, 0.f);
            }
        }
        __syncthreads();
        #pragma unroll
        for (int p = 0; p < 3; p++) {
            const __nv_bfloat16* Ap = (p == 2) ? Al : Ah;
            const __nv_bfloat16* Bp = (p == 1) ? Bl : Bh;
            #pragma unroll
            for (int ks = 0; ks < 2; ks++) {
                wmma::fragment<wmma::matrix_a, 16, 16, 16, __nv_bfloat16, wmma::row_major> fa[4];
                wmma::fragment<wmma::matrix_b, 16, 16, 16, __nv_bfloat16, wmma::col_major> fb[2];
                #pragma unroll
                for (int i = 0; i < 4; i++)
                    wmma::load_matrix_sync(fa[i], Ap + (wm * 64 + i * 16) * SP + ks * 16, SP);
                #pragma unroll
                for (int j = 0; j < 2; j++)
                    wmma::load_matrix_sync(fb[j], Bp + (wn * 32 + j * 16) * SP + ks * 16, SP);
                #pragma unroll
                for (int i = 0; i < 4; i++)
                    #pragma unroll
                    for (int j = 0; j < 2; j++)
                        wmma::mma_sync(acc[i][j], fa[i], fb[j], acc[i][j]);
            }
        }
    }
    __syncthreads();
    float* Cs = (float*)smc;  // 128 x 136
    #pragma unroll
    for (int i = 0; i < 4; i++)
        #pragma unroll
        for (int j = 0; j < 2; j++)
            wmma::store_matrix_sync(Cs + (wm * 64 + i * 16) * 136 + wn * 32 + j * 16,
                                    acc[i][j], 136, wmma::mem_row_major);
    __syncthreads();
    for (int i = tid; i < 128 * 128; i += 256) {
        int r = i >> 7, c = i & 127;
        if (n0 + c < N) C[(long long)r * N + n0 + c] = Cs[r * 136 + c] + bias[n0 + c];
    }
}

// ===== fused GEMM2: ep = tanh(enc[128,512] @ Wc[256,512]^T + b); sc = tanh(ep . hd) + mask =====
// 512 threads (16 warps, 4m x 4n), block tile 128x256, BK=32, prefetch pipelined.
#define F_CS 135168
#define F_SMEM 137216

__global__ void __launch_bounds__(512) tc_gemm2_fused(const float* __restrict__ enc,
                                                      const float* __restrict__ Wc,
                                                      const float* __restrict__ Wc_b,
                                                      const float* __restrict__ hd,
                                                      const int* __restrict__ idxs,
                                                      float* __restrict__ sc) {
    extern __shared__ char smc[];
    __nv_bfloat16* Ah = (__nv_bfloat16*)smc;
    __nv_bfloat16* Al = Ah + 128 * SP;
    __nv_bfloat16* Bh = Al + 128 * SP;
    __nv_bfloat16* Bl = Bh + 256 * SP;
    float* sh_hd = (float*)(smc + F_CS);
    const int tid = threadIdx.x, wid = tid >> 5;
    const int wm = wid & 3, wn = wid >> 2;   // warp tile 32(m) x 64(n)
    const int g0 = blockIdx.x * 128;
    const int bA = g0 / T, bB = (g0 + 127) / T;
    const float* Abase = enc + (long long)g0 * TWOH;

    for (int i = tid; i < 512; i += 512)
        sh_hd[i] = hd[(size_t)((i < 256) ? bA : bB) * H + (i & 255)];

    // A: 2 quads/thread, B: 4 quads/thread
    int ar[2], ac[2], br[4], bc[4];
    #pragma unroll
    for (int j = 0; j < 2; j++) { int i = tid + j * 512; ar[j] = i >> 3; ac[j] = (i & 7) << 2; }
    #pragma unroll
    for (int j = 0; j < 4; j++) { int i = tid + j * 512; br[j] = i >> 3; bc[j] = (i & 7) << 2; }

    float4 pa[2], pb[4];
    #pragma unroll
    for (int j = 0; j < 2; j++) pa[j] = *(const float4*)(Abase + (long long)ar[j] * TWOH + ac[j]);
    #pragma unroll
    for (int j = 0; j < 4; j++) pb[j] = *(const float4*)(Wc + (long long)br[j] * TWOH + bc[j]);

    wmma::fragment<wmma::accumulator, 16, 16, 16, float> acc[2][4];
    #pragma unroll
    for (int i = 0; i < 2; i++)
        #pragma unroll
        for (int j = 0; j < 4; j++) wmma::fill_fragment(acc[i][j], 0.0f);

    for (int kk = 0; kk < TWOH; kk += 32) {
        __syncthreads();
        #pragma unroll
        for (int j = 0; j < 2; j++) store_split(pa[j], Ah, Al, ar[j], ac[j]);
        #pragma unroll
        for (int j = 0; j < 4; j++) store_split(pb[j], Bh, Bl, br[j], bc[j]);
        int kn = kk + 32;
        if (kn < TWOH) {
            #pragma unroll
            for (int j = 0; j < 2; j++)
                pa[j] = *(const float4*)(Abase + (long long)ar[j] * TWOH + kn + ac[j]);
            #pragma unroll
            for (int j = 0; j < 4; j++)
                pb[j] = *(const float4*)(Wc + (long long)br[j] * TWOH + kn + bc[j]);
        }
        __syncthreads();
        #pragma unroll
        for (int p = 0; p < 3; p++) {
            const __nv_bfloat16* Ap = (p == 2) ? Al : Ah;
            const __nv_bfloat16* Bp = (p == 1) ? Bl : Bh;
            #pragma unroll
            for (int ks = 0; ks < 2; ks++) {
                wmma::fragment<wmma::matrix_a, 16, 16, 16, __nv_bfloat16, wmma::row_major> fa[2];
                wmma::fragment<wmma::matrix_b, 16, 16, 16, __nv_bfloat16, wmma::col_major> fb[4];
                #pragma unroll
                for (int i = 0; i < 2; i++)
                    wmma::load_matrix_sync(fa[i], Ap + (wm * 32 + i * 16) * SP + ks * 16, SP);
                #pragma unroll
                for (int j = 0; j < 4; j++)
                    wmma::load_matrix_sync(fb[j], Bp + (wn * 64 + j * 16) * SP + ks * 16, SP);
                #pragma unroll
                for (int i = 0; i < 2; i++)
                    #pragma unroll
                    for (int j = 0; j < 4; j++)
                        wmma::mma_sync(acc[i][j], fa[i], fb[j], acc[i][j]);
            }
        }
    }
    __syncthreads();
    float* Cs = (float*)smc;  // 128 x 264
    #pragma unroll
    for (int i = 0; i < 2; i++)
        #pragma unroll
        for (int j = 0; j < 4; j++)
            wmma::store_matrix_sync(Cs + (wm * 32 + i * 16) * 264 + wn * 64 + j * 16,
                                    acc[i][j], 264, wmma::mem_row_major);
    __syncthreads();

    // fused epilogue: fast tanh(+bias), dot with hd, quad-reduce, tanh, mask
    int row = tid >> 2, q = tid & 3;
    int g = g0 + row;
    int hsel = ((g / T) == bA) ? 0 : 256;
    float partial = 0.f;
    #pragma unroll 8
    for (int c = q * 64; c < q * 64 + 64; c++) {
        float v = ftanh(Cs[row * 264 + c] + Wc_b[c]);
        partial += v * sh_hd[hsel + c];
    }
    partial += __shfl_xor_sync(0xffffffffu, partial, 1);
    partial += __shfl_xor_sync(0xffffffffu, partial, 2);
    if (q == 0) {
        float v = tanhf(partial);
        if (idxs[g] == 0) v -= 10000.0f;
        sc[g] = v;
    }
}

// ---------------- prep ----------------
__global__ void prep_kernel(const int* __restrict__ dec, const float* __restrict__ enc,
                            const float* __restrict__ prev, const float* __restrict__ selr,
                            const int* __restrict__ stepp, const float* __restrict__ emb,
                            const float* __restrict__ Wi_w, const float* __restrict__ Wi_b,
                            float* __restrict__ pv, float* __restrict__ gin) {
    int b = blockIdx.x;
    int tid = threadIdx.x; // 512
    int step = stepp ? *stepp : 1;
    __shared__ float se[TWOH];
    if (step != 0) {
        gin[(size_t)b * GIN + tid] = selr[(size_t)b * TWOH + tid];
        if (tid < H) pv[b * H + tid] = prev[b * H + tid];
    } else {
        gin[(size_t)b * GIN + tid] = 0.0f;
        se[tid] = enc[((size_t)b * T + (T - 1)) * TWOH + tid];
        __syncthreads();
        if (tid < H) {
            float s = Wi_b[tid];
            #pragma unroll 8
            for (int k = 0; k < TWOH; k++) s += se[k] * Wi_w[tid * TWOH + k];
            pv[b * H + tid] = s;
        }
    }
    if (tid < EDIM) gin[(size_t)b * GIN + TWOH + tid] = emb[(size_t)dec[b] * EDIM + tid];
}

// ---------------- GRU gates (small count: keep accurate math) ----------------
__global__ void gate_kernel(const float* __restrict__ gi, const float* __restrict__ gh,
                            const float* __restrict__ pv, float* __restrict__ hdo,
                            float* __restrict__ out) {
    int b = blockIdx.x, j = threadIdx.x;
    const float* gib = gi + (size_t)b * G3;
    const float* ghb = gh + (size_t)b * G3;
    float r = 1.0f / (1.0f + expf(-(gib[j] + ghb[j])));
    float z = 1.0f / (1.0f + expf(-(gib[H + j] + ghb[H + j])));
    float n = tanhf(gib[2 * H + j] + r * ghb[2 * H + j]);
    float h = (1.0f - z) * n + z * pv[b * H + j];
    hdo[b * H + j] = h;
    out[OFF_H + (size_t)b * H + j] = h;
}

// ---------------- joint softmax row reduce: two-pass, fast exp ----------------
__global__ void rowreduce_kernel(const float* __restrict__ sg, const float* __restrict__ sc,
                                 float* __restrict__ rmax, float* __restrict__ rsum) {
    int b = blockIdx.x, tid = threadIdx.x; // 512
    const int total = V + T;
    const float* rowg = sg + (size_t)b * V;
    const float* rowc = sc + b * T;
    __shared__ float red[512];

    float m = -INFINITY;
    for (int j = tid; j < total; j += 512)
        m = fmaxf(m, (j < V) ? rowg[j] : rowc[j - V]);
    red[tid] = m;
    __syncthreads();
    for (int st = 256; st > 0; st >>= 1) {
        if (tid < st) red[tid] = fmaxf(red[tid], red[tid + st]);
        __syncthreads();
    }
    float M = red[0];
    __syncthreads();

    float s = 0.0f;
    for (int j = tid; j < total; j += 512)
        s += __expf(((j < V) ? rowg[j] : rowc[j - V]) - M);
    red[tid] = s;
    __syncthreads();
    for (int st = 256; st > 0; st >>= 1) {
        if (tid < st) red[tid] += red[tid + st];
        __syncthreads();
    }
    if (tid == 0) { rmax[b] = M; rsum[b] = red[0]; }
}

// ---------------- prob_out base ----------------
__global__ void prob_kernel(const float* __restrict__ sg, const float* __restrict__ rmax,
                            const float* __restrict__ rsum, float* __restrict__ out) {
    int b = blockIdx.y;
    int j = blockIdx.x * 256 + threadIdx.x;
    if (j >= OV) return;
    float m = rmax[b], inv = __fdividef(1.0f, rsum[b]);
    out[(size_t)b * OV + j] = (j < V) ? __expf(sg[(size_t)b * V + j] - m) * inv : 0.0001f;
}

// ---------------- scatter copy probs ----------------
__global__ void scatter_kernel(const float* __restrict__ sc, const int* __restrict__ idxs,
                               const float* __restrict__ rmax, const float* __restrict__ rsum,
                               float* __restrict__ out) {
    int i = blockIdx.x * 256 + threadIdx.x;
    if (i >= B * T) return;
    int b = i / T;
    float p = __expf(sc[i] - rmax[b]) * __fdividef(1.0f, rsum[b]);
    atomicAdd(&out[(size_t)b * OV + idxs[i]], p);
}

// ---------------- selective read ----------------
__global__ void selread_kernel(const float* __restrict__ sc, const int* __restrict__ idxs,
                               const int* __restrict__ dec, const float* __restrict__ enc,
                               const float* __restrict__ rmax, const float* __restrict__ rsum,
                               float* __restrict__ out) {
    int b = blockIdx.x, tid = threadIdx.x;
    __shared__ int s_cnt;
    __shared__ int s_ts[T];
    __shared__ float s_w[T];
    if (tid == 0) {
        int d = dec[b];
        int cnt = 0;
        float m = rmax[b], inv = __fdividef(1.0f, rsum[b]);
        for (int t = 0; t < T; t++) {
            if (idxs[b * T + t] == d) {
                s_ts[cnt] = t;
                s_w[cnt] = __expf(sc[b * T + t] - m) * inv;
                cnt++;
            }
        }
        s_cnt = cnt;
    }
    __syncthreads();
    int cnt = s_cnt;
    float scale = (cnt > 1) ? (1.0f / (float)cnt) : 1.0f;
    for (int e = tid; e < TWOH; e += 256) {
        float acc = 0.0f;
        for (int i = 0; i < cnt; i++)
            acc += s_w[i] * enc[((size_t)b * T + s_ts[i]) * TWOH + e];
        out[OFF_S + (size_t)b * TWOH + e] = acc * scale;
    }
}

// ---------------- launch ----------------
extern "C" void kernel_launch(void* const* d_in, const int* in_sizes, int n_in,
                              void* d_out, int out_size) {
    int o = (n_in >= 17) ? 0 : -1;
    const int*   dec   = (const int*)d_in[0];
    const float* enc   = (const float*)d_in[1];
    const int*   idxs  = (const int*)d_in[2];
    const float* prev  = (const float*)d_in[3];
    const float* selr  = (const float*)d_in[4];
    const int*   stepp = (o == 0) ? (const int*)d_in[5] : nullptr;
    const float* emb   = (const float*)d_in[6 + o];
    const float* W_ih  = (const float*)d_in[7 + o];
    const float* W_hh  = (const float*)d_in[8 + o];
    const float* b_ih  = (const float*)d_in[9 + o];
    const float* b_hh  = (const float*)d_in[10 + o];
    const float* Wi_w  = (const float*)d_in[11 + o];
    const float* Wi_b  = (const float*)d_in[12 + o];
    const float* Wg_w  = (const float*)d_in[13 + o];
    const float* Wg_b  = (const float*)d_in[14 + o];
    const float* Wc_w  = (const float*)d_in[15 + o];
    const float* Wc_b  = (const float*)d_in[16 + o];
    float* out = (float*)d_out;

    float *sg, *sc, *gin, *gi, *gh, *pv, *hd, *rmax, *rsum;
    cudaGetSymbolAddress((void**)&sg,   g_score_g);
    cudaGetSymbolAddress((void**)&sc,   g_score_c);
    cudaGetSymbolAddress((void**)&gin,  g_gin);
    cudaGetSymbolAddress((void**)&gi,   g_gi);
    cudaGetSymbolAddress((void**)&gh,   g_gh);
    cudaGetSymbolAddress((void**)&pv,   g_prev);
    cudaGetSymbolAddress((void**)&hd,   g_hid);
    cudaGetSymbolAddress((void**)&rmax, g_rmax);
    cudaGetSymbolAddress((void**)&rsum, g_rsum);

    cudaFuncSetAttribute(tc_gemm1, cudaFuncAttributeMaxDynamicSharedMemorySize, G1_SMEM);
    cudaFuncSetAttribute(tc_gemm2_fused, cudaFuncAttributeMaxDynamicSharedMemorySize, F_SMEM);

    // 1. step handling + embedding gather + gru_in assembly
    prep_kernel<<<B, 512>>>(dec, enc, prev, selr, stepp, emb, Wi_w, Wi_b, pv, gin);
    // 2. GRU projections (HMMA, split-bf16)
    tc_gemm1<<<G3 / 128, 256, G1_SMEM>>>(gin, W_ih, b_ih, gi, G3, GIN);
    tc_gemm1<<<G3 / 128, 256, G1_SMEM>>>(pv, W_hh, b_hh, gh, G3, H);
    // 3. gates -> decode_hidden
    gate_kernel<<<B, H>>>(gi, gh, pv, hd, out);
    // 4. generation scores [128 x 50257]
    tc_gemm1<<<(V + 127) / 128, 256, G1_SMEM>>>(hd, Wg_w, Wg_b, sg, V, H);
    // 5+6. enc projection + tanh + copy-score dot + tanh + mask, fused
    tc_gemm2_fused<<<(B * T) / 128, 512, F_SMEM>>>(enc, Wc_w, Wc_b, hd, idxs, sc);
    // 7. joint softmax stats (two-pass, fast exp)
    rowreduce_kernel<<<B, 512>>>(sg, sc, rmax, rsum);
    // 8. prob_out base
    prob_kernel<<<dim3((OV + 255) / 256, B), 256>>>(sg, rmax, rsum, out);
    // 9. scatter-add copy probs
    scatter_kernel<<<(B * T + 255) / 256, 256>>>(sc, idxs, rmax, rsum, out);
    // 10. selective read
    selread_kernel<<<B, 256>>>(sc, idxs, dec, enc, rmax, rsum, out);
}